// round 10
// baseline (speedup 1.0000x reference)
#include <cuda_runtime.h>
#include <cuda_bf16.h>
#include <cstdint>

// Problem constants
#define BATCH    2097152
#define TILE_B   128               // rows per CTA (8 warps x 16 rows)
#define NTILES   (BATCH / TILE_B)  // 16384
#define NTHREADS 256

// ---------- helpers ----------

__device__ __forceinline__ uint32_t pkb(__nv_bfloat16 a, __nv_bfloat16 b) {
    __nv_bfloat162 p; p.x = a; p.y = b;
    return *reinterpret_cast<uint32_t*>(&p);
}

// split (a,b) into bf16 hi-pack and lo-pack (2-term split, ~2^-18 rel accuracy)
__device__ __forceinline__ void splitpk(float a, float b, uint32_t& hi, uint32_t& lo) {
    __nv_bfloat16 ah = __float2bfloat16_rn(a);
    __nv_bfloat16 bh = __float2bfloat16_rn(b);
    __nv_bfloat16 al = __float2bfloat16_rn(a - __bfloat162float(ah));
    __nv_bfloat16 bl = __float2bfloat16_rn(b - __bfloat162float(bh));
    hi = pkb(ah, bh);
    lo = pkb(al, bl);
}

// ---- fast gates (steps 0-2): single-MUFU tanh (MUFU.TANH) ----
__device__ __forceinline__ float ftanh_a(float x) {
    float r;
    asm("tanh.approx.f32 %0, %1;" : "=f"(r) : "f"(x));
    return r;
}
__device__ __forceinline__ float fsig_a(float x) {
    return fmaf(0.5f, ftanh_a(0.5f * x), 0.5f);
}

// ---- accurate gates (final step): 2-MUFU ex2+rcp forms (~1e-6 rel) ----
__device__ __forceinline__ float fsig_x(float x) {
    float e, r;
    asm("ex2.approx.f32 %0, %1;" : "=f"(e) : "f"(-1.4426950408889634f * x));
    asm("rcp.approx.f32 %0, %1;" : "=f"(r) : "f"(1.0f + e));
    return r;
}
__device__ __forceinline__ float ftanh_x(float x) {
    float e, r;
    asm("ex2.approx.f32 %0, %1;" : "=f"(e) : "f"(2.8853900817779268f * x));
    asm("rcp.approx.f32 %0, %1;" : "=f"(r) : "f"(1.0f + e));
    return 1.0f - 2.0f * r;
}

__device__ __forceinline__ void mma16816(float* d, const uint32_t* a, const uint32_t* b) {
    asm volatile(
        "mma.sync.aligned.m16n8k16.row.col.f32.bf16.bf16.f32 "
        "{%0,%1,%2,%3}, {%4,%5,%6,%7}, {%8,%9}, {%0,%1,%2,%3};\n"
        : "+f"(d[0]), "+f"(d[1]), "+f"(d[2]), "+f"(d[3])
        : "r"(a[0]), "r"(a[1]), "r"(a[2]), "r"(a[3]),
          "r"(b[0]), "r"(b[1]));
}

// one 16-wide K-tile against all 16 N-tiles (128 gate columns)
__device__ __forceinline__ void gemm_row(float acc[16][4], const uint32_t a[4],
                                         const uint2 wrow[16][32], int lane) {
#pragma unroll
    for (int nn = 0; nn < 16; nn++) {
        uint2 b = wrow[nn][lane];
        mma16816(acc[nn], a, reinterpret_cast<const uint32_t*>(&b));
    }
}

// ---------- kernel ----------

__global__ void __launch_bounds__(NTHREADS, 2)
lstm4_kernel(const float* __restrict__ X,   // [B,32]
             const float* __restrict__ H0,  // [B,32]
             const float* __restrict__ C0,  // [B,32]
             const float* __restrict__ Wih, // [128,32]
             const float* __restrict__ Whh, // [128,32]
             const float* __restrict__ bih, // [128]
             const float* __restrict__ bhh, // [128]
             float* __restrict__ out)       // [B,32]
{
    // Pre-swizzled B fragments:
    // region kk: 0,1=Wih_hi  2,3=Wih_lo  4,5=Whh_hi  6,7=Whh_lo
    // (kk&1 selects K-halves 0-15 / 16-31 of the 32-wide K dim)
    __shared__ uint2  wfrag[8][16][32];   // 32 KB
    __shared__ float  bias_s[128];

    for (int e = threadIdx.x; e < 8 * 16 * 32; e += NTHREADS) {
        int ln = e & 31, nn = (e >> 5) & 15, kk = e >> 9;
        int tt = ln & 3, gg = ln >> 2;
        int n  = nn * 8 + gg;
        const float* W = (kk < 4) ? Wih : Whh;
        int wantlo = (kk >> 1) & 1;
        int kb = (kk & 1) * 16 + 2 * tt;
        float v0 = W[n * 32 + kb],     v1 = W[n * 32 + kb + 1];
        float v2 = W[n * 32 + kb + 8], v3 = W[n * 32 + kb + 9];
        uint32_t h0p, l0p, h1p, l1p;
        splitpk(v0, v1, h0p, l0p);
        splitpk(v2, v3, h1p, l1p);
        uint2 r;
        r.x = wantlo ? l0p : h0p;
        r.y = wantlo ? l1p : h1p;
        wfrag[kk][nn][ln] = r;
    }
    if (threadIdx.x < 128) bias_s[threadIdx.x] = bih[threadIdx.x] + bhh[threadIdx.x];
    __syncthreads();

    const int lane = threadIdx.x & 31;
    const int wrp  = threadIdx.x >> 5;
    const int gid  = lane >> 2;   // groupID: row within 8
    const int t4   = lane & 3;    // thread-in-group: column pair selector

    const size_t r0 = (size_t)blockIdx.x * TILE_B + wrp * 16 + gid;
    const size_t r1 = r0 + 8;

    // ---- accumulators = bias ----
    float acc[16][4];
#pragma unroll
    for (int nn = 0; nn < 16; nn++) {
        float2 b = *(const float2*)(bias_s + nn * 8 + 2 * t4);
        acc[nn][0] = b.x; acc[nn][1] = b.y; acc[nn][2] = b.x; acc[nn][3] = b.y;
    }

    // ---- phase 1: x fragments (built directly from loads), x GEMMs ----
    uint32_t fhi[2][4], flo[2][4];
#pragma unroll
    for (int kt = 0; kt < 2; kt++) {
        int co = kt * 16 + 2 * t4;
        float2 a0 = *(const float2*)(X + r0 * 32 + co);
        float2 a1 = *(const float2*)(X + r1 * 32 + co);
        float2 a2 = *(const float2*)(X + r0 * 32 + co + 8);
        float2 a3 = *(const float2*)(X + r1 * 32 + co + 8);
        splitpk(a0.x, a0.y, fhi[kt][0], flo[kt][0]);
        splitpk(a1.x, a1.y, fhi[kt][1], flo[kt][1]);
        splitpk(a2.x, a2.y, fhi[kt][2], flo[kt][2]);
        splitpk(a3.x, a3.y, fhi[kt][3], flo[kt][3]);
    }
    gemm_row(acc, fhi[0], wfrag[0], lane);
    gemm_row(acc, fhi[1], wfrag[1], lane);
    gemm_row(acc, flo[0], wfrag[0], lane);
    gemm_row(acc, flo[1], wfrag[1], lane);
    gemm_row(acc, fhi[0], wfrag[2], lane);
    gemm_row(acc, fhi[1], wfrag[3], lane);

    // ---- phase 2: h0 fragments (reuse regs), capture h_prev, h GEMMs ----
    float hp[4][4];
#pragma unroll
    for (int kt = 0; kt < 2; kt++) {
        int co = kt * 16 + 2 * t4;
        float2 a0 = *(const float2*)(H0 + r0 * 32 + co);
        float2 a1 = *(const float2*)(H0 + r1 * 32 + co);
        float2 a2 = *(const float2*)(H0 + r0 * 32 + co + 8);
        float2 a3 = *(const float2*)(H0 + r1 * 32 + co + 8);
        int gb = 2 * kt;
        hp[gb][0]   = a0.x; hp[gb][1]   = a0.y;
        hp[gb][2]   = a1.x; hp[gb][3]   = a1.y;
        hp[gb+1][0] = a2.x; hp[gb+1][1] = a2.y;
        hp[gb+1][2] = a3.x; hp[gb+1][3] = a3.y;
        splitpk(a0.x, a0.y, fhi[kt][0], flo[kt][0]);
        splitpk(a1.x, a1.y, fhi[kt][1], flo[kt][1]);
        splitpk(a2.x, a2.y, fhi[kt][2], flo[kt][2]);
        splitpk(a3.x, a3.y, fhi[kt][3], flo[kt][3]);
    }
    gemm_row(acc, fhi[0], wfrag[4], lane);
    gemm_row(acc, fhi[1], wfrag[5], lane);
    gemm_row(acc, flo[0], wfrag[4], lane);
    gemm_row(acc, flo[1], wfrag[5], lane);
    gemm_row(acc, fhi[0], wfrag[6], lane);
    gemm_row(acc, fhi[1], wfrag[7], lane);

    // ---- cell state ----
    float cst[4][4];
#pragma unroll
    for (int grp = 0; grp < 4; grp++) {
        int co = grp * 8 + 2 * t4;
        float2 c0 = *(const float2*)(C0 + r0 * 32 + co);
        float2 c1 = *(const float2*)(C0 + r1 * 32 + co);
        cst[grp][0] = c0.x; cst[grp][1] = c0.y;
        cst[grp][2] = c1.x; cst[grp][3] = c1.y;
    }

    // ---- 4 recurrent steps; accumulator updated with (h_t - h_{t-1}) @ Whh^T ----
    // Steps 0-2: fast MUFU.TANH gates (errors damped through the recurrence).
    // Step 3 (output step): accurate ex2+rcp gates (error lands in out directly).
#pragma unroll
    for (int step = 0; step < 4; step++) {
        const bool fast = (step < 3);
        float dl[4][4];
#pragma unroll
        for (int grp = 0; grp < 4; grp++) {
#pragma unroll
            for (int idx = 0; idx < 4; idx++) {
                float ga = acc[grp][idx];        // i: cols 0..31
                float gf = acc[4 + grp][idx];    // f: cols 32..63
                float gg = acc[8 + grp][idx];    // g: cols 64..95
                float go = acc[12 + grp][idx];   // o: cols 96..127
                float ii = fast ? fsig_a(ga) : fsig_x(ga);
                float ff = fast ? fsig_a(gf) : fsig_x(gf);
                float tg = fast ? ftanh_a(gg) : ftanh_x(gg);
                float oo = fast ? fsig_a(go) : fsig_x(go);
                float c  = ff * cst[grp][idx] + ii * tg;
                cst[grp][idx] = c;
                float tc = fast ? ftanh_a(c) : ftanh_x(c);
                float h  = oo * tc;
                h = (h >= 0.0f) ? h : 0.01f * h;          // LeakyReLU
                dl[grp][idx] = h - hp[grp][idx];
                hp[grp][idx] = h;
            }
        }
        if (step < 3) {
#pragma unroll
            for (int kt = 0; kt < 2; kt++) {
                int gb = 2 * kt;
                splitpk(dl[gb][0],   dl[gb][1],   fhi[kt][0], flo[kt][0]);
                splitpk(dl[gb][2],   dl[gb][3],   fhi[kt][1], flo[kt][1]);
                splitpk(dl[gb+1][0], dl[gb+1][1], fhi[kt][2], flo[kt][2]);
                splitpk(dl[gb+1][2], dl[gb+1][3], fhi[kt][3], flo[kt][3]);
            }
            gemm_row(acc, fhi[0], wfrag[4], lane);
            gemm_row(acc, fhi[1], wfrag[5], lane);
            gemm_row(acc, flo[0], wfrag[4], lane);
            gemm_row(acc, flo[1], wfrag[5], lane);
            gemm_row(acc, fhi[0], wfrag[6], lane);
            gemm_row(acc, fhi[1], wfrag[7], lane);
        }
    }

    // ---- store final h ----
#pragma unroll
    for (int grp = 0; grp < 4; grp++) {
        int co = grp * 8 + 2 * t4;
        *(float2*)(out + r0 * 32 + co) = make_float2(hp[grp][0], hp[grp][1]);
        *(float2*)(out + r1 * 32 + co) = make_float2(hp[grp][2], hp[grp][3]);
    }
}

// ---------- launch ----------

extern "C" void kernel_launch(void* const* d_in, const int* in_sizes, int n_in,
                              void* d_out, int out_size) {
    const float* X   = (const float*)d_in[0];
    const float* H0  = (const float*)d_in[1];
    const float* C0  = (const float*)d_in[2];
    const float* Wih = (const float*)d_in[3];
    const float* Whh = (const float*)d_in[4];
    const float* bih = (const float*)d_in[5];
    const float* bhh = (const float*)d_in[6];
    lstm4_kernel<<<NTILES, NTHREADS>>>(X, H0, C0, Wih, Whh, bih, bhh, (float*)d_out);
}

// round 12
// speedup vs baseline: 1.5779x; 1.5779x over previous
#include <cuda_runtime.h>
#include <cuda_bf16.h>
#include <cstdint>

// Problem constants
#define BATCH    2097152
#define TILE_B   64                // rows per CTA (4 warps x 16 rows)
#define NTILES   (BATCH / TILE_B)  // 32768
#define NTHREADS 128
#define NGRID    444               // 148 SMs x 3 resident CTAs, persistent

// ---------- helpers ----------

__device__ __forceinline__ uint32_t pkb(__nv_bfloat16 a, __nv_bfloat16 b) {
    __nv_bfloat162 p; p.x = a; p.y = b;
    return *reinterpret_cast<uint32_t*>(&p);
}

// split (a,b) into bf16 hi-pack and lo-pack (2-term split, ~2^-18 rel accuracy)
__device__ __forceinline__ void splitpk(float a, float b, uint32_t& hi, uint32_t& lo) {
    __nv_bfloat16 ah = __float2bfloat16_rn(a);
    __nv_bfloat16 bh = __float2bfloat16_rn(b);
    __nv_bfloat16 al = __float2bfloat16_rn(a - __bfloat162float(ah));
    __nv_bfloat16 bl = __float2bfloat16_rn(b - __bfloat162float(bh));
    hi = pkb(ah, bh);
    lo = pkb(al, bl);
}

// ---- fast gates (steps 0-2): single-MUFU tanh (MUFU.TANH) ----
__device__ __forceinline__ float ftanh_a(float x) {
    float r;
    asm("tanh.approx.f32 %0, %1;" : "=f"(r) : "f"(x));
    return r;
}
__device__ __forceinline__ float fsig_a(float x) {
    return fmaf(0.5f, ftanh_a(0.5f * x), 0.5f);
}

// ---- accurate gates (final step): 2-MUFU ex2+rcp forms (~1e-6 rel) ----
__device__ __forceinline__ float fsig_x(float x) {
    float e, r;
    asm("ex2.approx.f32 %0, %1;" : "=f"(e) : "f"(-1.4426950408889634f * x));
    asm("rcp.approx.f32 %0, %1;" : "=f"(r) : "f"(1.0f + e));
    return r;
}
__device__ __forceinline__ float ftanh_x(float x) {
    float e, r;
    asm("ex2.approx.f32 %0, %1;" : "=f"(e) : "f"(2.8853900817779268f * x));
    asm("rcp.approx.f32 %0, %1;" : "=f"(r) : "f"(1.0f + e));
    return 1.0f - 2.0f * r;
}

__device__ __forceinline__ void mma16816(float* d, const uint32_t* a, const uint32_t* b) {
    asm volatile(
        "mma.sync.aligned.m16n8k16.row.col.f32.bf16.bf16.f32 "
        "{%0,%1,%2,%3}, {%4,%5,%6,%7}, {%8,%9}, {%0,%1,%2,%3};\n"
        : "+f"(d[0]), "+f"(d[1]), "+f"(d[2]), "+f"(d[3])
        : "r"(a[0]), "r"(a[1]), "r"(a[2]), "r"(a[3]),
          "r"(b[0]), "r"(b[1]));
}

// one 16-wide K-tile against all 16 N-tiles (128 gate columns)
__device__ __forceinline__ void gemm_row(float acc[16][4], const uint32_t a[4],
                                         const uint2 wrow[16][32], int lane) {
#pragma unroll
    for (int nn = 0; nn < 16; nn++) {
        uint2 b = wrow[nn][lane];
        mma16816(acc[nn], a, reinterpret_cast<const uint32_t*>(&b));
    }
}

// ---------- kernel ----------

__global__ void __launch_bounds__(NTHREADS, 3)
lstm4_kernel(const float* __restrict__ X,   // [B,32]
             const float* __restrict__ H0,  // [B,32]
             const float* __restrict__ C0,  // [B,32]
             const float* __restrict__ Wih, // [128,32]
             const float* __restrict__ Whh, // [128,32]
             const float* __restrict__ bih, // [128]
             const float* __restrict__ bhh, // [128]
             float* __restrict__ out)       // [B,32]
{
    // Pre-swizzled B fragments:
    // region kk: 0,1=Wih_hi  2,3=Wih_lo  4,5=Whh_hi  6,7=Whh_lo
    // (kk&1 selects K-halves 0-15 / 16-31 of the 32-wide K dim)
    __shared__ uint2  wfrag[8][16][32];   // 32 KB
    __shared__ float  bias_s[128];

    for (int e = threadIdx.x; e < 8 * 16 * 32; e += NTHREADS) {
        int ln = e & 31, nn = (e >> 5) & 15, kk = e >> 9;
        int tt = ln & 3, gg = ln >> 2;
        int n  = nn * 8 + gg;
        const float* W = (kk < 4) ? Wih : Whh;
        int wantlo = (kk >> 1) & 1;
        int kb = (kk & 1) * 16 + 2 * tt;
        float v0 = W[n * 32 + kb],     v1 = W[n * 32 + kb + 1];
        float v2 = W[n * 32 + kb + 8], v3 = W[n * 32 + kb + 9];
        uint32_t h0p, l0p, h1p, l1p;
        splitpk(v0, v1, h0p, l0p);
        splitpk(v2, v3, h1p, l1p);
        uint2 r;
        r.x = wantlo ? l0p : h0p;
        r.y = wantlo ? l1p : h1p;
        wfrag[kk][nn][ln] = r;
    }
    bias_s[threadIdx.x] = bih[threadIdx.x] + bhh[threadIdx.x];
    __syncthreads();

    const int lane = threadIdx.x & 31;
    const int wrp  = threadIdx.x >> 5;   // 0..3
    const int gid  = lane >> 2;   // groupID: row within 8
    const int t4   = lane & 3;    // thread-in-group: column pair selector

    for (int tile = blockIdx.x; tile < NTILES; tile += NGRID) {
        const size_t r0 = (size_t)tile * TILE_B + wrp * 16 + gid;
        const size_t r1 = r0 + 8;

        // ---- accumulators = bias ----
        float acc[16][4];
#pragma unroll
        for (int nn = 0; nn < 16; nn++) {
            float2 b = *(const float2*)(bias_s + nn * 8 + 2 * t4);
            acc[nn][0] = b.x; acc[nn][1] = b.y; acc[nn][2] = b.x; acc[nn][3] = b.y;
        }

        // ---- phase 1: x fragments (built directly from loads), x GEMMs ----
        uint32_t fhi[2][4], flo[2][4];
#pragma unroll
        for (int kt = 0; kt < 2; kt++) {
            int co = kt * 16 + 2 * t4;
            float2 a0 = *(const float2*)(X + r0 * 32 + co);
            float2 a1 = *(const float2*)(X + r1 * 32 + co);
            float2 a2 = *(const float2*)(X + r0 * 32 + co + 8);
            float2 a3 = *(const float2*)(X + r1 * 32 + co + 8);
            splitpk(a0.x, a0.y, fhi[kt][0], flo[kt][0]);
            splitpk(a1.x, a1.y, fhi[kt][1], flo[kt][1]);
            splitpk(a2.x, a2.y, fhi[kt][2], flo[kt][2]);
            splitpk(a3.x, a3.y, fhi[kt][3], flo[kt][3]);
        }
        gemm_row(acc, fhi[0], wfrag[0], lane);
        gemm_row(acc, fhi[1], wfrag[1], lane);
        gemm_row(acc, flo[0], wfrag[0], lane);
        gemm_row(acc, flo[1], wfrag[1], lane);
        gemm_row(acc, fhi[0], wfrag[2], lane);
        gemm_row(acc, fhi[1], wfrag[3], lane);

        // ---- phase 2: h0 fragments (reuse regs), capture h_prev, h GEMMs ----
        float hp[4][4];
#pragma unroll
        for (int kt = 0; kt < 2; kt++) {
            int co = kt * 16 + 2 * t4;
            float2 a0 = *(const float2*)(H0 + r0 * 32 + co);
            float2 a1 = *(const float2*)(H0 + r1 * 32 + co);
            float2 a2 = *(const float2*)(H0 + r0 * 32 + co + 8);
            float2 a3 = *(const float2*)(H0 + r1 * 32 + co + 8);
            int gb = 2 * kt;
            hp[gb][0]   = a0.x; hp[gb][1]   = a0.y;
            hp[gb][2]   = a1.x; hp[gb][3]   = a1.y;
            hp[gb+1][0] = a2.x; hp[gb+1][1] = a2.y;
            hp[gb+1][2] = a3.x; hp[gb+1][3] = a3.y;
            splitpk(a0.x, a0.y, fhi[kt][0], flo[kt][0]);
            splitpk(a1.x, a1.y, fhi[kt][1], flo[kt][1]);
            splitpk(a2.x, a2.y, fhi[kt][2], flo[kt][2]);
            splitpk(a3.x, a3.y, fhi[kt][3], flo[kt][3]);
        }
        gemm_row(acc, fhi[0], wfrag[4], lane);
        gemm_row(acc, fhi[1], wfrag[5], lane);
        gemm_row(acc, flo[0], wfrag[4], lane);
        gemm_row(acc, flo[1], wfrag[5], lane);
        gemm_row(acc, fhi[0], wfrag[6], lane);
        gemm_row(acc, fhi[1], wfrag[7], lane);

        // ---- cell state ----
        float cst[4][4];
#pragma unroll
        for (int grp = 0; grp < 4; grp++) {
            int co = grp * 8 + 2 * t4;
            float2 c0 = *(const float2*)(C0 + r0 * 32 + co);
            float2 c1 = *(const float2*)(C0 + r1 * 32 + co);
            cst[grp][0] = c0.x; cst[grp][1] = c0.y;
            cst[grp][2] = c1.x; cst[grp][3] = c1.y;
        }

        // ---- 4 recurrent steps; accumulator updated with (h_t - h_{t-1}) @ Whh^T ----
        // Steps 0-2: fast MUFU.TANH gates (measured: ~1e-7 impact on rel_err).
        // Step 3 (output step): accurate ex2+rcp gates.
#pragma unroll
        for (int step = 0; step < 4; step++) {
            const bool fast = (step < 3);
            float dl[4][4];
#pragma unroll
            for (int grp = 0; grp < 4; grp++) {
#pragma unroll
                for (int idx = 0; idx < 4; idx++) {
                    float ga = acc[grp][idx];        // i: cols 0..31
                    float gf = acc[4 + grp][idx];    // f: cols 32..63
                    float gg = acc[8 + grp][idx];    // g: cols 64..95
                    float go = acc[12 + grp][idx];   // o: cols 96..127
                    float ii = fast ? fsig_a(ga) : fsig_x(ga);
                    float ff = fast ? fsig_a(gf) : fsig_x(gf);
                    float tg = fast ? ftanh_a(gg) : ftanh_x(gg);
                    float oo = fast ? fsig_a(go) : fsig_x(go);
                    float c  = ff * cst[grp][idx] + ii * tg;
                    cst[grp][idx] = c;
                    float tc = fast ? ftanh_a(c) : ftanh_x(c);
                    float h  = oo * tc;
                    h = (h >= 0.0f) ? h : 0.01f * h;          // LeakyReLU
                    dl[grp][idx] = h - hp[grp][idx];
                    hp[grp][idx] = h;
                }
            }
            if (step < 3) {
#pragma unroll
                for (int kt = 0; kt < 2; kt++) {
                    int gb = 2 * kt;
                    splitpk(dl[gb][0],   dl[gb][1],   fhi[kt][0], flo[kt][0]);
                    splitpk(dl[gb][2],   dl[gb][3],   fhi[kt][1], flo[kt][1]);
                    splitpk(dl[gb+1][0], dl[gb+1][1], fhi[kt][2], flo[kt][2]);
                    splitpk(dl[gb+1][2], dl[gb+1][3], fhi[kt][3], flo[kt][3]);
                }
                gemm_row(acc, fhi[0], wfrag[4], lane);
                gemm_row(acc, fhi[1], wfrag[5], lane);
                gemm_row(acc, flo[0], wfrag[4], lane);
                gemm_row(acc, flo[1], wfrag[5], lane);
                gemm_row(acc, fhi[0], wfrag[6], lane);
                gemm_row(acc, fhi[1], wfrag[7], lane);
            }
        }

        // ---- store final h ----
#pragma unroll
        for (int grp = 0; grp < 4; grp++) {
            int co = grp * 8 + 2 * t4;
            *(float2*)(out + r0 * 32 + co) = make_float2(hp[grp][0], hp[grp][1]);
            *(float2*)(out + r1 * 32 + co) = make_float2(hp[grp][2], hp[grp][3]);
        }
    }
}

// ---------- launch ----------

extern "C" void kernel_launch(void* const* d_in, const int* in_sizes, int n_in,
                              void* d_out, int out_size) {
    const float* X   = (const float*)d_in[0];
    const float* H0  = (const float*)d_in[1];
    const float* C0  = (const float*)d_in[2];
    const float* Wih = (const float*)d_in[3];
    const float* Whh = (const float*)d_in[4];
    const float* bih = (const float*)d_in[5];
    const float* bhh = (const float*)d_in[6];
    lstm4_kernel<<<NGRID, NTHREADS>>>(X, H0, C0, Wih, Whh, bih, bhh, (float*)d_out);
}

// round 13
// speedup vs baseline: 1.5813x; 1.0022x over previous
#include <cuda_runtime.h>
#include <cuda_bf16.h>
#include <cstdint>

// Problem constants
#define BATCH    2097152
#define TILE_B   64                // rows per CTA (4 warps x 16 rows)
#define NTILES   (BATCH / TILE_B)  // 32768
#define NTHREADS 128
#define NGRID    444               // 148 SMs x 3 resident CTAs, persistent

// ---------- helpers ----------

__device__ __forceinline__ uint32_t pkb(__nv_bfloat16 a, __nv_bfloat16 b) {
    __nv_bfloat162 p; p.x = a; p.y = b;
    return *reinterpret_cast<uint32_t*>(&p);
}

// split (a,b) into bf16 hi-pack and lo-pack (2-term split, ~2^-18 rel accuracy)
__device__ __forceinline__ void splitpk(float a, float b, uint32_t& hi, uint32_t& lo) {
    __nv_bfloat16 ah = __float2bfloat16_rn(a);
    __nv_bfloat16 bh = __float2bfloat16_rn(b);
    __nv_bfloat16 al = __float2bfloat16_rn(a - __bfloat162float(ah));
    __nv_bfloat16 bl = __float2bfloat16_rn(b - __bfloat162float(bh));
    hi = pkb(ah, bh);
    lo = pkb(al, bl);
}

// ---- fast gates (steps 0-2): single-MUFU tanh (MUFU.TANH) ----
__device__ __forceinline__ float ftanh_a(float x) {
    float r;
    asm("tanh.approx.f32 %0, %1;" : "=f"(r) : "f"(x));
    return r;
}
__device__ __forceinline__ float fsig_a(float x) {
    return fmaf(0.5f, ftanh_a(0.5f * x), 0.5f);
}

// ---- accurate gates (final step): 2-MUFU ex2+rcp forms (~1e-6 rel) ----
__device__ __forceinline__ float fsig_x(float x) {
    float e, r;
    asm("ex2.approx.f32 %0, %1;" : "=f"(e) : "f"(-1.4426950408889634f * x));
    asm("rcp.approx.f32 %0, %1;" : "=f"(r) : "f"(1.0f + e));
    return r;
}
__device__ __forceinline__ float ftanh_x(float x) {
    float e, r;
    asm("ex2.approx.f32 %0, %1;" : "=f"(e) : "f"(2.8853900817779268f * x));
    asm("rcp.approx.f32 %0, %1;" : "=f"(r) : "f"(1.0f + e));
    return 1.0f - 2.0f * r;
}

__device__ __forceinline__ void mma16816(float* d, const uint32_t* a, const uint32_t* b) {
    asm volatile(
        "mma.sync.aligned.m16n8k16.row.col.f32.bf16.bf16.f32 "
        "{%0,%1,%2,%3}, {%4,%5,%6,%7}, {%8,%9}, {%0,%1,%2,%3};\n"
        : "+f"(d[0]), "+f"(d[1]), "+f"(d[2]), "+f"(d[3])
        : "r"(a[0]), "r"(a[1]), "r"(a[2]), "r"(a[3]),
          "r"(b[0]), "r"(b[1]));
}

// one 16-wide K-tile against all 16 N-tiles (128 gate columns)
__device__ __forceinline__ void gemm_row(float acc[16][4], const uint32_t a[4],
                                         const uint2 wrow[16][32], int lane) {
#pragma unroll
    for (int nn = 0; nn < 16; nn++) {
        uint2 b = wrow[nn][lane];
        mma16816(acc[nn], a, reinterpret_cast<const uint32_t*>(&b));
    }
}

// ---------- kernel ----------

__global__ void __launch_bounds__(NTHREADS, 3)
lstm4_kernel(const float* __restrict__ X,   // [B,32]
             const float* __restrict__ H0,  // [B,32]
             const float* __restrict__ C0,  // [B,32]
             const float* __restrict__ Wih, // [128,32]
             const float* __restrict__ Whh, // [128,32]
             const float* __restrict__ bih, // [128]
             const float* __restrict__ bhh, // [128]
             float* __restrict__ out)       // [B,32]
{
    // Pre-swizzled B fragments:
    // region kk: 0,1=Wih_hi  2,3=Wih_lo  4,5=Whh_hi  6,7=Whh_lo
    // (kk&1 selects K-halves 0-15 / 16-31 of the 32-wide K dim)
    __shared__ uint2  wfrag[8][16][32];   // 32 KB
    __shared__ float  bias_s[128];

    for (int e = threadIdx.x; e < 8 * 16 * 32; e += NTHREADS) {
        int ln = e & 31, nn = (e >> 5) & 15, kk = e >> 9;
        int tt = ln & 3, gg = ln >> 2;
        int n  = nn * 8 + gg;
        const float* W = (kk < 4) ? Wih : Whh;
        int wantlo = (kk >> 1) & 1;
        int kb = (kk & 1) * 16 + 2 * tt;
        float v0 = W[n * 32 + kb],     v1 = W[n * 32 + kb + 1];
        float v2 = W[n * 32 + kb + 8], v3 = W[n * 32 + kb + 9];
        uint32_t h0p, l0p, h1p, l1p;
        splitpk(v0, v1, h0p, l0p);
        splitpk(v2, v3, h1p, l1p);
        uint2 r;
        r.x = wantlo ? l0p : h0p;
        r.y = wantlo ? l1p : h1p;
        wfrag[kk][nn][ln] = r;
    }
    bias_s[threadIdx.x] = bih[threadIdx.x] + bhh[threadIdx.x];
    __syncthreads();

    const int lane = threadIdx.x & 31;
    const int wrp  = threadIdx.x >> 5;   // 0..3
    const int gid  = lane >> 2;   // groupID: row within 8
    const int t4   = lane & 3;    // thread-in-group: column pair selector

    for (int tile = blockIdx.x; tile < NTILES; tile += NGRID) {
        const size_t r0 = (size_t)tile * TILE_B + wrp * 16 + gid;
        const size_t r1 = r0 + 8;

        // ---- accumulators = bias ----
        float acc[16][4];
#pragma unroll
        for (int nn = 0; nn < 16; nn++) {
            float2 b = *(const float2*)(bias_s + nn * 8 + 2 * t4);
            acc[nn][0] = b.x; acc[nn][1] = b.y; acc[nn][2] = b.x; acc[nn][3] = b.y;
        }

        // ---- phase 1: x fragments (built directly from loads), x GEMMs ----
        uint32_t fhi[2][4], flo[2][4];
#pragma unroll
        for (int kt = 0; kt < 2; kt++) {
            int co = kt * 16 + 2 * t4;
            float2 a0 = *(const float2*)(X + r0 * 32 + co);
            float2 a1 = *(const float2*)(X + r1 * 32 + co);
            float2 a2 = *(const float2*)(X + r0 * 32 + co + 8);
            float2 a3 = *(const float2*)(X + r1 * 32 + co + 8);
            splitpk(a0.x, a0.y, fhi[kt][0], flo[kt][0]);
            splitpk(a1.x, a1.y, fhi[kt][1], flo[kt][1]);
            splitpk(a2.x, a2.y, fhi[kt][2], flo[kt][2]);
            splitpk(a3.x, a3.y, fhi[kt][3], flo[kt][3]);
        }
        gemm_row(acc, fhi[0], wfrag[0], lane);
        gemm_row(acc, fhi[1], wfrag[1], lane);
        gemm_row(acc, flo[0], wfrag[0], lane);
        gemm_row(acc, flo[1], wfrag[1], lane);
        gemm_row(acc, fhi[0], wfrag[2], lane);
        gemm_row(acc, fhi[1], wfrag[3], lane);

        // ---- phase 2: h0 fragments (reuse regs), capture h_prev, h GEMMs ----
        float hp[4][4];
#pragma unroll
        for (int kt = 0; kt < 2; kt++) {
            int co = kt * 16 + 2 * t4;
            float2 a0 = *(const float2*)(H0 + r0 * 32 + co);
            float2 a1 = *(const float2*)(H0 + r1 * 32 + co);
            float2 a2 = *(const float2*)(H0 + r0 * 32 + co + 8);
            float2 a3 = *(const float2*)(H0 + r1 * 32 + co + 8);
            int gb = 2 * kt;
            hp[gb][0]   = a0.x; hp[gb][1]   = a0.y;
            hp[gb][2]   = a1.x; hp[gb][3]   = a1.y;
            hp[gb+1][0] = a2.x; hp[gb+1][1] = a2.y;
            hp[gb+1][2] = a3.x; hp[gb+1][3] = a3.y;
            splitpk(a0.x, a0.y, fhi[kt][0], flo[kt][0]);
            splitpk(a1.x, a1.y, fhi[kt][1], flo[kt][1]);
            splitpk(a2.x, a2.y, fhi[kt][2], flo[kt][2]);
            splitpk(a3.x, a3.y, fhi[kt][3], flo[kt][3]);
        }
        gemm_row(acc, fhi[0], wfrag[4], lane);
        gemm_row(acc, fhi[1], wfrag[5], lane);
        gemm_row(acc, flo[0], wfrag[4], lane);
        gemm_row(acc, flo[1], wfrag[5], lane);
        gemm_row(acc, fhi[0], wfrag[6], lane);
        gemm_row(acc, fhi[1], wfrag[7], lane);

        // ---- cell state ----
        float cst[4][4];
#pragma unroll
        for (int grp = 0; grp < 4; grp++) {
            int co = grp * 8 + 2 * t4;
            float2 c0 = *(const float2*)(C0 + r0 * 32 + co);
            float2 c1 = *(const float2*)(C0 + r1 * 32 + co);
            cst[grp][0] = c0.x; cst[grp][1] = c0.y;
            cst[grp][2] = c1.x; cst[grp][3] = c1.y;
        }

        // ---- 4 recurrent steps; accumulator updated with (h_t - h_{t-1}) @ Whh^T ----
        // Deltas are split-packed straight into the (dead) fragment registers —
        // no dl[4][4] staging array (R12: regs pinned at cap -> spills).
        // Steps 0-2: fast MUFU.TANH gates (measured: ~1e-7 impact on rel_err).
        // Step 3 (output step): accurate ex2+rcp gates.
#pragma unroll
        for (int step = 0; step < 4; step++) {
            const bool fast = (step < 3);
#pragma unroll
            for (int kt = 0; kt < 2; kt++) {
#pragma unroll
                for (int g2 = 0; g2 < 2; g2++) {
                    const int grp = 2 * kt + g2;
                    float d[4];
#pragma unroll
                    for (int idx = 0; idx < 4; idx++) {
                        float ga = acc[grp][idx];        // i: cols 0..31
                        float gf = acc[4 + grp][idx];    // f: cols 32..63
                        float gg = acc[8 + grp][idx];    // g: cols 64..95
                        float go = acc[12 + grp][idx];   // o: cols 96..127
                        float ii = fast ? fsig_a(ga) : fsig_x(ga);
                        float ff = fast ? fsig_a(gf) : fsig_x(gf);
                        float tg = fast ? ftanh_a(gg) : ftanh_x(gg);
                        float oo = fast ? fsig_a(go) : fsig_x(go);
                        float c  = ff * cst[grp][idx] + ii * tg;
                        cst[grp][idx] = c;
                        float tc = fast ? ftanh_a(c) : ftanh_x(c);
                        float h  = oo * tc;
                        h = (h >= 0.0f) ? h : 0.01f * h;  // LeakyReLU
                        d[idx] = h - hp[grp][idx];
                        hp[grp][idx] = h;
                    }
                    if (step < 3) {
                        splitpk(d[0], d[1], fhi[kt][2 * g2],     flo[kt][2 * g2]);
                        splitpk(d[2], d[3], fhi[kt][2 * g2 + 1], flo[kt][2 * g2 + 1]);
                    }
                }
            }
            if (step < 3) {
                gemm_row(acc, fhi[0], wfrag[4], lane);
                gemm_row(acc, fhi[1], wfrag[5], lane);
                gemm_row(acc, flo[0], wfrag[4], lane);
                gemm_row(acc, flo[1], wfrag[5], lane);
                gemm_row(acc, fhi[0], wfrag[6], lane);
                gemm_row(acc, fhi[1], wfrag[7], lane);
            }
        }

        // ---- store final h ----
#pragma unroll
        for (int grp = 0; grp < 4; grp++) {
            int co = grp * 8 + 2 * t4;
            *(float2*)(out + r0 * 32 + co) = make_float2(hp[grp][0], hp[grp][1]);
            *(float2*)(out + r1 * 32 + co) = make_float2(hp[grp][2], hp[grp][3]);
        }
    }
}

// ---------- launch ----------

extern "C" void kernel_launch(void* const* d_in, const int* in_sizes, int n_in,
                              void* d_out, int out_size) {
    const float* X   = (const float*)d_in[0];
    const float* H0  = (const float*)d_in[1];
    const float* C0  = (const float*)d_in[2];
    const float* Wih = (const float*)d_in[3];
    const float* Whh = (const float*)d_in[4];
    const float* bih = (const float*)d_in[5];
    const float* bhh = (const float*)d_in[6];
    lstm4_kernel<<<NGRID, NTHREADS>>>(X, H0, C0, Wih, Whh, bih, bhh, (float*)d_out);
}

// round 16
// speedup vs baseline: 1.6365x; 1.0349x over previous
#include <cuda_runtime.h>
#include <cuda_bf16.h>
#include <cstdint>

// Problem constants
#define BATCH    2097152
#define TILE_B   64                // rows per CTA (4 warps x 16 rows)
#define NTILES   (BATCH / TILE_B)  // 32768
#define NTHREADS 128
#define NGRID    444               // 148 SMs x 3 resident CTAs, persistent

// ---------- helpers ----------

__device__ __forceinline__ uint32_t pkb(__nv_bfloat16 a, __nv_bfloat16 b) {
    __nv_bfloat162 p; p.x = a; p.y = b;
    return *reinterpret_cast<uint32_t*>(&p);
}

// split (a,b) into bf16 hi-pack and lo-pack (2-term split, ~2^-18 rel accuracy)
__device__ __forceinline__ void splitpk(float a, float b, uint32_t& hi, uint32_t& lo) {
    __nv_bfloat16 ah = __float2bfloat16_rn(a);
    __nv_bfloat16 bh = __float2bfloat16_rn(b);
    __nv_bfloat16 al = __float2bfloat16_rn(a - __bfloat162float(ah));
    __nv_bfloat16 bl = __float2bfloat16_rn(b - __bfloat162float(bh));
    hi = pkb(ah, bh);
    lo = pkb(al, bl);
}

// ---- fast gates (steps 0-2): single-MUFU tanh (MUFU.TANH) ----
__device__ __forceinline__ float ftanh_a(float x) {
    float r;
    asm("tanh.approx.f32 %0, %1;" : "=f"(r) : "f"(x));
    return r;
}
__device__ __forceinline__ float fsig_a(float x) {
    return fmaf(0.5f, ftanh_a(0.5f * x), 0.5f);
}

// ---- accurate gates (final step): 2-MUFU ex2+rcp forms (~1e-6 rel) ----
__device__ __forceinline__ float fsig_x(float x) {
    float e, r;
    asm("ex2.approx.f32 %0, %1;" : "=f"(e) : "f"(-1.4426950408889634f * x));
    asm("rcp.approx.f32 %0, %1;" : "=f"(r) : "f"(1.0f + e));
    return r;
}
__device__ __forceinline__ float ftanh_x(float x) {
    float e, r;
    asm("ex2.approx.f32 %0, %1;" : "=f"(e) : "f"(2.8853900817779268f * x));
    asm("rcp.approx.f32 %0, %1;" : "=f"(r) : "f"(1.0f + e));
    return 1.0f - 2.0f * r;
}

__device__ __forceinline__ void mma16816(float* d, const uint32_t* a, const uint32_t* b) {
    asm volatile(
        "mma.sync.aligned.m16n8k16.row.col.f32.bf16.bf16.f32 "
        "{%0,%1,%2,%3}, {%4,%5,%6,%7}, {%8,%9}, {%0,%1,%2,%3};\n"
        : "+f"(d[0]), "+f"(d[1]), "+f"(d[2]), "+f"(d[3])
        : "r"(a[0]), "r"(a[1]), "r"(a[2]), "r"(a[3]),
          "r"(b[0]), "r"(b[1]));
}

// one 16-wide K-tile against all 16 N-tiles, ONE A operand
__device__ __forceinline__ void gemm_row(float acc[16][4], const uint32_t a[4],
                                         const uint2 wrow[16][32], int lane) {
#pragma unroll
    for (int nn = 0; nn < 16; nn++) {
        uint2 b = wrow[nn][lane];
        mma16816(acc[nn], a, reinterpret_cast<const uint32_t*>(&b));
    }
}

// same, but TWO A operands sharing one B load (halves LDS for paired terms)
__device__ __forceinline__ void gemm_row2(float acc[16][4],
                                          const uint32_t a1[4], const uint32_t a2[4],
                                          const uint2 wrow[16][32], int lane) {
#pragma unroll
    for (int nn = 0; nn < 16; nn++) {
        uint2 b = wrow[nn][lane];
        mma16816(acc[nn], a1, reinterpret_cast<const uint32_t*>(&b));
        mma16816(acc[nn], a2, reinterpret_cast<const uint32_t*>(&b));
    }
}

// ---------- kernel ----------

__global__ void __launch_bounds__(NTHREADS, 3)
lstm4_kernel(const float* __restrict__ X,   // [B,32]
             const float* __restrict__ H0,  // [B,32]
             const float* __restrict__ C0,  // [B,32]
             const float* __restrict__ Wih, // [128,32]
             const float* __restrict__ Whh, // [128,32]
             const float* __restrict__ bih, // [128]
             const float* __restrict__ bhh, // [128]
             float* __restrict__ out)       // [B,32]
{
    // Pre-swizzled B fragments:
    // region kk: 0,1=Wih_hi  2,3=Wih_lo  4,5=Whh_hi  6,7=Whh_lo
    // (kk&1 selects K-halves 0-15 / 16-31 of the 32-wide K dim)
    __shared__ uint2  wfrag[8][16][32];   // 32 KB
    __shared__ float  bias_s[128];

    for (int e = threadIdx.x; e < 8 * 16 * 32; e += NTHREADS) {
        int ln = e & 31, nn = (e >> 5) & 15, kk = e >> 9;
        int tt = ln & 3, gg = ln >> 2;
        int n  = nn * 8 + gg;
        const float* W = (kk < 4) ? Wih : Whh;
        int wantlo = (kk >> 1) & 1;
        int kb = (kk & 1) * 16 + 2 * tt;
        float v0 = W[n * 32 + kb],     v1 = W[n * 32 + kb + 1];
        float v2 = W[n * 32 + kb + 8], v3 = W[n * 32 + kb + 9];
        uint32_t h0p, l0p, h1p, l1p;
        splitpk(v0, v1, h0p, l0p);
        splitpk(v2, v3, h1p, l1p);
        uint2 r;
        r.x = wantlo ? l0p : h0p;
        r.y = wantlo ? l1p : h1p;
        wfrag[kk][nn][ln] = r;
    }
    bias_s[threadIdx.x] = bih[threadIdx.x] + bhh[threadIdx.x];
    __syncthreads();

    const int lane = threadIdx.x & 31;
    const int wrp  = threadIdx.x >> 5;   // 0..3
    const int gid  = lane >> 2;   // groupID: row within 8
    const int t4   = lane & 3;    // thread-in-group: column pair selector

    for (int tile = blockIdx.x; tile < NTILES; tile += NGRID) {
        const size_t r0 = (size_t)tile * TILE_B + wrp * 16 + gid;
        const size_t r1 = r0 + 8;

        // ---- accumulators = bias ----
        float acc[16][4];
#pragma unroll
        for (int nn = 0; nn < 16; nn++) {
            float2 b = *(const float2*)(bias_s + nn * 8 + 2 * t4);
            acc[nn][0] = b.x; acc[nn][1] = b.y; acc[nn][2] = b.x; acc[nn][3] = b.y;
        }

        // ---- phase 1: x fragments (built directly from loads), x GEMMs ----
        uint32_t fhi[2][4], flo[2][4];
#pragma unroll
        for (int kt = 0; kt < 2; kt++) {
            int co = kt * 16 + 2 * t4;
            float2 a0 = *(const float2*)(X + r0 * 32 + co);
            float2 a1 = *(const float2*)(X + r1 * 32 + co);
            float2 a2 = *(const float2*)(X + r0 * 32 + co + 8);
            float2 a3 = *(const float2*)(X + r1 * 32 + co + 8);
            splitpk(a0.x, a0.y, fhi[kt][0], flo[kt][0]);
            splitpk(a1.x, a1.y, fhi[kt][1], flo[kt][1]);
            splitpk(a2.x, a2.y, fhi[kt][2], flo[kt][2]);
            splitpk(a3.x, a3.y, fhi[kt][3], flo[kt][3]);
        }
        gemm_row2(acc, fhi[0], flo[0], wfrag[0], lane);   // hi+lo share bank 0
        gemm_row2(acc, fhi[1], flo[1], wfrag[1], lane);   // hi+lo share bank 1
        gemm_row (acc, fhi[0],          wfrag[2], lane);  // hi x W_lo
        gemm_row (acc, fhi[1],          wfrag[3], lane);

        // ---- phase 2: h0 fragments (reuse regs), capture h_prev, h GEMMs ----
        float hp[4][4];
#pragma unroll
        for (int kt = 0; kt < 2; kt++) {
            int co = kt * 16 + 2 * t4;
            float2 a0 = *(const float2*)(H0 + r0 * 32 + co);
            float2 a1 = *(const float2*)(H0 + r1 * 32 + co);
            float2 a2 = *(const float2*)(H0 + r0 * 32 + co + 8);
            float2 a3 = *(const float2*)(H0 + r1 * 32 + co + 8);
            int gb = 2 * kt;
            hp[gb][0]   = a0.x; hp[gb][1]   = a0.y;
            hp[gb][2]   = a1.x; hp[gb][3]   = a1.y;
            hp[gb+1][0] = a2.x; hp[gb+1][1] = a2.y;
            hp[gb+1][2] = a3.x; hp[gb+1][3] = a3.y;
            splitpk(a0.x, a0.y, fhi[kt][0], flo[kt][0]);
            splitpk(a1.x, a1.y, fhi[kt][1], flo[kt][1]);
            splitpk(a2.x, a2.y, fhi[kt][2], flo[kt][2]);
            splitpk(a3.x, a3.y, fhi[kt][3], flo[kt][3]);
        }
        gemm_row2(acc, fhi[0], flo[0], wfrag[4], lane);
        gemm_row2(acc, fhi[1], flo[1], wfrag[5], lane);
        gemm_row (acc, fhi[0],          wfrag[6], lane);
        gemm_row (acc, fhi[1],          wfrag[7], lane);

        // ---- cell state ----
        float cst[4][4];
#pragma unroll
        for (int grp = 0; grp < 4; grp++) {
            int co = grp * 8 + 2 * t4;
            float2 c0 = *(const float2*)(C0 + r0 * 32 + co);
            float2 c1 = *(const float2*)(C0 + r1 * 32 + co);
            cst[grp][0] = c0.x; cst[grp][1] = c0.y;
            cst[grp][2] = c1.x; cst[grp][3] = c1.y;
        }

        // ---- 4 recurrent steps; accumulator updated with (h_t - h_{t-1}) @ Whh^T ----
        // Deltas are split-packed straight into the (dead) fragment registers.
        // Steps 0-2: fast MUFU.TANH gates (measured: ~1e-7 impact on rel_err).
        // Step 3 (output step): accurate ex2+rcp gates.
#pragma unroll
        for (int step = 0; step < 4; step++) {
            const bool fast = (step < 3);
#pragma unroll
            for (int kt = 0; kt < 2; kt++) {
#pragma unroll
                for (int g2 = 0; g2 < 2; g2++) {
                    const int grp = 2 * kt + g2;
                    float d[4];
#pragma unroll
                    for (int idx = 0; idx < 4; idx++) {
                        float ga = acc[grp][idx];        // i: cols 0..31
                        float gf = acc[4 + grp][idx];    // f: cols 32..63
                        float gg = acc[8 + grp][idx];    // g: cols 64..95
                        float go = acc[12 + grp][idx];   // o: cols 96..127
                        float ii = fast ? fsig_a(ga) : fsig_x(ga);
                        float ff = fast ? fsig_a(gf) : fsig_x(gf);
                        float tg = fast ? ftanh_a(gg) : ftanh_x(gg);
                        float oo = fast ? fsig_a(go) : fsig_x(go);
                        float c  = ff * cst[grp][idx] + ii * tg;
                        cst[grp][idx] = c;
                        float tc = fast ? ftanh_a(c) : ftanh_x(c);
                        float h  = oo * tc;
                        h = (h >= 0.0f) ? h : 0.01f * h;  // LeakyReLU
                        d[idx] = h - hp[grp][idx];
                        hp[grp][idx] = h;
                    }
                    if (step < 3) {
                        splitpk(d[0], d[1], fhi[kt][2 * g2],     flo[kt][2 * g2]);
                        splitpk(d[2], d[3], fhi[kt][2 * g2 + 1], flo[kt][2 * g2 + 1]);
                    }
                }
            }
            if (step < 3) {
                gemm_row2(acc, fhi[0], flo[0], wfrag[4], lane);
                gemm_row2(acc, fhi[1], flo[1], wfrag[5], lane);
                gemm_row (acc, fhi[0],          wfrag[6], lane);
                gemm_row (acc, fhi[1],          wfrag[7], lane);
            }
        }

        // ---- store final h ----
#pragma unroll
        for (int grp = 0; grp < 4; grp++) {
            int co = grp * 8 + 2 * t4;
            *(float2*)(out + r0 * 32 + co) = make_float2(hp[grp][0], hp[grp][1]);
            *(float2*)(out + r1 * 32 + co) = make_float2(hp[grp][2], hp[grp][3]);
        }
    }
}

// ---------- launch ----------

extern "C" void kernel_launch(void* const* d_in, const int* in_sizes, int n_in,
                              void* d_out, int out_size) {
    const float* X   = (const float*)d_in[0];
    const float* H0  = (const float*)d_in[1];
    const float* C0  = (const float*)d_in[2];
    const float* Wih = (const float*)d_in[3];
    const float* Whh = (const float*)d_in[4];
    const float* bih = (const float*)d_in[5];
    const float* bhh = (const float*)d_in[6];
    lstm4_kernel<<<NGRID, NTHREADS>>>(X, H0, C0, Whh == Whh ? Wih : Wih, Whh, bih, bhh, (float*)d_out);
}